// round 4
// baseline (speedup 1.0000x reference)
#include <cuda_runtime.h>

#define N_NODES 50000
#define N_EDGES 640000
#define D 128
#define KTOT 384          // concat width: [nfeats | sum_n/c | sum_e/c]
#define M_PAD 50048       // 391 * 128, GEMM M padding

// ---------------- scratch (static __device__ globals; no allocs) -------------
__device__ int   g_cnt[N_NODES];
__device__ int   g_off[N_NODES + 1];
__device__ int   g_cur[N_NODES];
__device__ int   g_eid[N_EDGES];
__device__ float g_flag[N_NODES];         // 1.0 if node has >=1 in-edge
__device__ float g_bias2[D];              // Wa2 @ b_msg
__device__ float g_Wc[KTOT * D];          // combined weight, TRANSPOSED: g_Wc[k*D + o]
__device__ float g_X[(size_t)M_PAD * KTOT]; // fused GEMM input (pad rows stay 0 from .bss)

// ---------------- K0: zero counts -------------------------------------------
__global__ void zero_kernel() {
    int i = blockIdx.x * blockDim.x + threadIdx.x;
    if (i < N_NODES) g_cnt[i] = 0;
}

// ---------------- K1: weight composition ------------------------------------
// Wc[o][0:128]    = Wa[o][0:128]                         (acts on nfeats)
// Wc[o][128+i]    = sum_j Wa[o][128+j] * Wmsg[j][i]      (i in 0..255)
// bias2[o]        = sum_j Wa[o][128+j] * bmsg[j]
// stored transposed: g_Wc[k*D + o]
__global__ void wc_kernel(const float* __restrict__ Wm,
                          const float* __restrict__ bm,
                          const float* __restrict__ Wa) {
    __shared__ float wa2[128];
    int o = blockIdx.x;           // 0..127
    int t = threadIdx.x;          // 0..255
    if (t < 128) wa2[t] = Wa[o * 256 + 128 + t];
    __syncthreads();
    if (t < 128) g_Wc[t * D + o] = Wa[o * 256 + t];
    float s = 0.f;
#pragma unroll 4
    for (int j = 0; j < 128; j++) s += wa2[j] * Wm[j * 256 + t];
    g_Wc[(128 + t) * D + o] = s;
    if (t == 0) {
        float b = 0.f;
        for (int j = 0; j < 128; j++) b += wa2[j] * bm[j];
        g_bias2[o] = b;
    }
}

// ---------------- K2: histogram dst -----------------------------------------
__global__ void count_kernel(const int* __restrict__ dst) {
    int i = blockIdx.x * blockDim.x + threadIdx.x;
    if (i < N_EDGES) atomicAdd(&g_cnt[dst[i]], 1);
}

// ---------------- K3: exclusive scan (single block, chunked) ----------------
__global__ void scan_kernel() {
    __shared__ int s[1024];
    __shared__ int carry;
    int t = threadIdx.x;
    if (t == 0) carry = 0;
    __syncthreads();
    for (int base = 0; base < N_NODES; base += 1024) {
        int i = base + t;
        int v = (i < N_NODES) ? g_cnt[i] : 0;
        s[t] = v;
        __syncthreads();
        for (int ofs = 1; ofs < 1024; ofs <<= 1) {
            int add = (t >= ofs) ? s[t - ofs] : 0;
            __syncthreads();
            s[t] += add;
            __syncthreads();
        }
        int excl = carry + s[t] - v;
        if (i < N_NODES) { g_off[i] = excl; g_cur[i] = excl; }
        __syncthreads();
        if (t == 0) carry += s[1023];
        __syncthreads();
    }
    if (t == 0) g_off[N_NODES] = carry;
}

// ---------------- K4: fill CSR edge lists -----------------------------------
__global__ void fill_kernel(const int* __restrict__ dst) {
    int i = blockIdx.x * blockDim.x + threadIdx.x;
    if (i < N_EDGES) {
        int v = dst[i];
        int p = atomicAdd(&g_cur[v], 1);
        g_eid[p] = i;
    }
}

// ---------------- K5: warp-per-node gather-sum + build X --------------------
// lane = float4 chunk of the 128-dim feature (32 lanes * 4 floats)
__global__ void gather_kernel(const float* __restrict__ nfeats,
                              const float* __restrict__ efeats,
                              const int* __restrict__ src) {
    int node = (blockIdx.x * blockDim.x + threadIdx.x) >> 5;
    int lane = threadIdx.x & 31;
    if (node >= N_NODES) return;
    int s = g_off[node];
    int e = g_off[node + 1];
    float4 an = make_float4(0.f, 0.f, 0.f, 0.f);
    float4 ae = make_float4(0.f, 0.f, 0.f, 0.f);
    for (int p = s; p < e; p++) {
        int eid = g_eid[p];
        int sv  = __ldg(&src[eid]);
        float4 nv = ((const float4*)(nfeats + (size_t)sv  * D))[lane];
        float4 ev = ((const float4*)(efeats + (size_t)eid * D))[lane];
        an.x += nv.x; an.y += nv.y; an.z += nv.z; an.w += nv.w;
        ae.x += ev.x; ae.y += ev.y; ae.z += ev.z; ae.w += ev.w;
    }
    float inv = 1.0f / (float)max(e - s, 1);
    an.x *= inv; an.y *= inv; an.z *= inv; an.w *= inv;
    ae.x *= inv; ae.y *= inv; ae.z *= inv; ae.w *= inv;
    float4 nf = ((const float4*)(nfeats + (size_t)node * D))[lane];
    float4* xr = (float4*)(g_X + (size_t)node * KTOT);
    xr[lane]      = nf;
    xr[32 + lane] = an;
    xr[64 + lane] = ae;
    if (lane == 0) g_flag[node] = (e > s) ? 1.0f : 0.0f;
}

// ---------------- K6: SGEMM [M_PAD x 384] @ [384 x 128] + epilogue ----------
// BM=128, BN=128 (full), BK=8, 256 threads, 8x8 per-thread micro-tile
__global__ __launch_bounds__(256) void gemm_kernel(const float* __restrict__ bias_a,
                                                   float* __restrict__ out) {
    __shared__ float As[8][128];
    __shared__ float Bs[8][128];
    const int tid = threadIdx.x;
    const int m0  = blockIdx.x * 128;
    const int tx  = tid & 15;          // 0..15 -> output cols tx*8..+7
    const int ty  = tid >> 4;          // 0..15 -> output rows ty*8..+7
    const int ar  = tid >> 1;          // A-load row 0..127
    const int ac  = (tid & 1) * 4;     // A-load col offset {0,4}
    const int bk  = tid >> 5;          // B-load k row 0..7
    const int bn  = (tid & 31) * 4;    // B-load col 0..124

    float acc[8][8];
#pragma unroll
    for (int i = 0; i < 8; i++)
#pragma unroll
        for (int j = 0; j < 8; j++) acc[i][j] = 0.f;

    const float* xrow = g_X + (size_t)(m0 + ar) * KTOT + ac;

    for (int k0 = 0; k0 < KTOT; k0 += 8) {
        float4 av = *(const float4*)(xrow + k0);
        float4 bv = *(const float4*)(g_Wc + (size_t)(k0 + bk) * D + bn);
        __syncthreads();
        As[ac + 0][ar] = av.x;
        As[ac + 1][ar] = av.y;
        As[ac + 2][ar] = av.z;
        As[ac + 3][ar] = av.w;
        *(float4*)&Bs[bk][bn] = bv;
        __syncthreads();
#pragma unroll
        for (int kk = 0; kk < 8; kk++) {
            float a[8], b[8];
            *(float4*)(a)     = *(const float4*)&As[kk][ty * 8];
            *(float4*)(a + 4) = *(const float4*)&As[kk][ty * 8 + 4];
            *(float4*)(b)     = *(const float4*)&Bs[kk][tx * 8];
            *(float4*)(b + 4) = *(const float4*)&Bs[kk][tx * 8 + 4];
#pragma unroll
            for (int i = 0; i < 8; i++)
#pragma unroll
                for (int j = 0; j < 8; j++) acc[i][j] += a[i] * b[j];
        }
    }

    // epilogue: relu(acc + b_a[n] + flag[m]*b2[n])
    float bb[8], b2[8];
#pragma unroll
    for (int j = 0; j < 8; j++) {
        int n = tx * 8 + j;
        bb[j] = bias_a[n];
        b2[j] = g_bias2[n];
    }
#pragma unroll
    for (int i = 0; i < 8; i++) {
        int m = m0 + ty * 8 + i;
        if (m < N_NODES) {
            float fl = g_flag[m];
            float r[8];
#pragma unroll
            for (int j = 0; j < 8; j++) {
                float v = acc[i][j] + bb[j] + fl * b2[j];
                r[j] = v > 0.f ? v : 0.f;
            }
            *(float4*)&out[(size_t)m * D + tx * 8]     = *(float4*)(r);
            *(float4*)&out[(size_t)m * D + tx * 8 + 4] = *(float4*)(r + 4);
        }
    }
}

// ---------------- launch -----------------------------------------------------
extern "C" void kernel_launch(void* const* d_in, const int* in_sizes, int n_in,
                              void* d_out, int out_size) {
    const float* nfeats = (const float*)d_in[0];
    const float* efeats = (const float*)d_in[1];
    const float* Wm     = (const float*)d_in[2];
    const float* bm     = (const float*)d_in[3];
    const float* Wa     = (const float*)d_in[4];
    const float* ba     = (const float*)d_in[5];
    const int*   src    = (const int*)d_in[6];
    const int*   dst    = (const int*)d_in[7];
    float* out = (float*)d_out;

    zero_kernel  <<<(N_NODES + 255) / 256, 256>>>();
    wc_kernel    <<<D, 256>>>(Wm, bm, Wa);
    count_kernel <<<(N_EDGES + 255) / 256, 256>>>(dst);
    scan_kernel  <<<1, 1024>>>();
    fill_kernel  <<<(N_EDGES + 255) / 256, 256>>>(dst);
    gather_kernel<<<(N_NODES * 32 + 255) / 256, 256>>>(nfeats, efeats, src);
    gemm_kernel  <<<M_PAD / 128, 256>>>(ba, out);
}

// round 5
// speedup vs baseline: 1.2804x; 1.2804x over previous
#include <cuda_runtime.h>

#define N_NODES 50000
#define N_EDGES 640000
#define D 128
#define KTOT 384          // concat width: [nfeats | sum_n/c | sum_e/c]
#define M_PAD 50048       // 391 * 128, GEMM M padding
#define NBLK_SCAN 49      // ceil(50000 / 1024)

typedef unsigned long long ull;

// ---------------- scratch (static __device__ globals; no allocs) -------------
__device__ int   g_cnt[N_NODES];
__device__ int   g_off[N_NODES + 1];
__device__ int   g_cur[N_NODES];
__device__ int   g_eid[N_EDGES];
__device__ int   g_bsum[64];
__device__ int   g_bpre[64];
__device__ float g_flag[N_NODES];         // 1.0 if node has >=1 in-edge
__device__ float g_bias2[D];              // Wa2 @ b_msg
__device__ float g_Wc[KTOT * D];          // combined weight, TRANSPOSED: g_Wc[k*D + o]
__device__ float g_X[(size_t)M_PAD * KTOT]; // fused GEMM input (pad rows stay 0 from .bss)

// ---------------- packed fp32x2 helpers (FFMA2: PTX-only on sm_103a) --------
__device__ __forceinline__ void fma2(ull &d, ull a, ull b) {
    asm("fma.rn.f32x2 %0, %1, %2, %0;" : "+l"(d) : "l"(a), "l"(b));
}
__device__ __forceinline__ ull pack_dup(float x) {
    ull r;
    unsigned xi = __float_as_uint(x);
    asm("mov.b64 %0, {%1, %1};" : "=l"(r) : "r"(xi));
    return r;
}
__device__ __forceinline__ void unpack2(ull v, float &lo, float &hi) {
    unsigned a, b;
    asm("mov.b64 {%0, %1}, %2;" : "=r"(a), "=r"(b) : "l"(v));
    lo = __uint_as_float(a); hi = __uint_as_float(b);
}

// ---------------- K0: zero counts -------------------------------------------
__global__ void zero_kernel() {
    int i = blockIdx.x * blockDim.x + threadIdx.x;
    if (i < N_NODES) g_cnt[i] = 0;
}

// ---------------- K1: weight composition ------------------------------------
__global__ void wc_kernel(const float* __restrict__ Wm,
                          const float* __restrict__ bm,
                          const float* __restrict__ Wa) {
    __shared__ float wa2[128];
    int o = blockIdx.x;           // 0..127
    int t = threadIdx.x;          // 0..255
    if (t < 128) wa2[t] = Wa[o * 256 + 128 + t];
    __syncthreads();
    if (t < 128) g_Wc[t * D + o] = Wa[o * 256 + t];
    float s = 0.f;
#pragma unroll 4
    for (int j = 0; j < 128; j++) s += wa2[j] * Wm[j * 256 + t];
    g_Wc[(128 + t) * D + o] = s;
    if (t == 0) {
        float b = 0.f;
        for (int j = 0; j < 128; j++) b += wa2[j] * bm[j];
        g_bias2[o] = b;
    }
}

// ---------------- K2: histogram dst -----------------------------------------
__global__ void count_kernel(const int* __restrict__ dst) {
    int i = blockIdx.x * blockDim.x + threadIdx.x;
    if (i < N_EDGES) atomicAdd(&g_cnt[dst[i]], 1);
}

// ---------------- K3a: per-block scan (49 blocks x 1024) --------------------
__global__ void scan1_kernel() {
    __shared__ int wsum[32];
    int t = threadIdx.x;
    int i = blockIdx.x * 1024 + t;
    int v = (i < N_NODES) ? g_cnt[i] : 0;
    int x = v;
#pragma unroll
    for (int o = 1; o < 32; o <<= 1) {
        int y = __shfl_up_sync(0xFFFFFFFFu, x, o);
        if ((t & 31) >= o) x += y;
    }
    if ((t & 31) == 31) wsum[t >> 5] = x;
    __syncthreads();
    if (t < 32) {
        int w = wsum[t];
#pragma unroll
        for (int o = 1; o < 32; o <<= 1) {
            int y = __shfl_up_sync(0xFFFFFFFFu, w, o);
            if (t >= o) w += y;
        }
        wsum[t] = w;
    }
    __syncthreads();
    int warp = t >> 5;
    int excl = x - v + (warp ? wsum[warp - 1] : 0);
    if (i < N_NODES) g_off[i] = excl;             // block-local exclusive
    if (t == 1023) g_bsum[blockIdx.x] = wsum[31]; // block total
}

// ---------------- K3b: scan the 49 block sums (1 warp) ----------------------
__global__ void scan2_kernel() {
    int t = threadIdx.x;                      // 0..31
    int a = g_bsum[t];                        // idx 0..31 (all < NBLK_SCAN)
    int b = (32 + t < NBLK_SCAN) ? g_bsum[32 + t] : 0;
    int ia = a, ib = b;
#pragma unroll
    for (int o = 1; o < 32; o <<= 1) {
        int ya = __shfl_up_sync(0xFFFFFFFFu, ia, o);
        int yb = __shfl_up_sync(0xFFFFFFFFu, ib, o);
        if (t >= o) { ia += ya; ib += yb; }
    }
    int tot = __shfl_sync(0xFFFFFFFFu, ia, 31);
    g_bpre[t] = ia - a;
    if (32 + t < NBLK_SCAN) g_bpre[32 + t] = tot + ib - b;
}

// ---------------- K3c: add block prefixes, init cursors ---------------------
__global__ void scan3_kernel() {
    int i = blockIdx.x * blockDim.x + threadIdx.x;
    if (i < N_NODES) {
        int o = g_off[i] + g_bpre[i >> 10];
        g_off[i] = o;
        g_cur[i] = o;
    }
    if (i == 0) g_off[N_NODES] = N_EDGES;   // total is always E
}

// ---------------- K4: fill CSR edge lists -----------------------------------
__global__ void fill_kernel(const int* __restrict__ dst) {
    int i = blockIdx.x * blockDim.x + threadIdx.x;
    if (i < N_EDGES) {
        int v = dst[i];
        int p = atomicAdd(&g_cur[v], 1);
        g_eid[p] = i;
    }
}

// ---------------- K5: warp-per-node gather-sum + build X --------------------
__global__ void gather_kernel(const float* __restrict__ nfeats,
                              const float* __restrict__ efeats,
                              const int* __restrict__ src) {
    int node = (blockIdx.x * blockDim.x + threadIdx.x) >> 5;
    int lane = threadIdx.x & 31;
    if (node >= N_NODES) return;
    int s = g_off[node];
    int e = g_off[node + 1];
    float4 an = make_float4(0.f, 0.f, 0.f, 0.f);
    float4 ae = make_float4(0.f, 0.f, 0.f, 0.f);
    for (int p = s; p < e; p++) {
        int eid = g_eid[p];
        int sv  = __ldg(&src[eid]);
        float4 nv = ((const float4*)(nfeats + (size_t)sv * D))[lane];     // L2-resident reuse
        float4 ev = __ldcs(((const float4*)(efeats + (size_t)eid * D)) + lane); // stream, evict-first
        an.x += nv.x; an.y += nv.y; an.z += nv.z; an.w += nv.w;
        ae.x += ev.x; ae.y += ev.y; ae.z += ev.z; ae.w += ev.w;
    }
    float inv = 1.0f / (float)max(e - s, 1);
    an.x *= inv; an.y *= inv; an.z *= inv; an.w *= inv;
    ae.x *= inv; ae.y *= inv; ae.z *= inv; ae.w *= inv;
    float4 nf = ((const float4*)(nfeats + (size_t)node * D))[lane];
    float4* xr = (float4*)(g_X + (size_t)node * KTOT);
    xr[lane]      = nf;
    xr[32 + lane] = an;
    xr[64 + lane] = ae;
    if (lane == 0) g_flag[node] = (e > s) ? 1.0f : 0.0f;
}

// ---------------- K6: SGEMM via packed FFMA2 + epilogue ---------------------
// BM=128, BN=128, BK=8, 256 threads, 8x8 per-thread micro-tile.
// Accumulators are fp32x2 pairs along the row (i) dim: acc2[ip][j] holds rows
// (2ip, 2ip+1). a-pairs read directly as 64-bit from As; b broadcast-packed.
__global__ __launch_bounds__(256, 2) void gemm_kernel(const float* __restrict__ bias_a,
                                                      float* __restrict__ out) {
    __shared__ float As[8][128];
    __shared__ float Bs[8][128];
    const int tid = threadIdx.x;
    const int m0  = blockIdx.x * 128;
    const int tx  = tid & 15;          // output cols tx*8..+7
    const int ty  = tid >> 4;          // output rows ty*8..+7
    const int ar  = tid >> 1;          // A-load row 0..127
    const int ac  = (tid & 1) * 4;     // A-load col offset {0,4}
    const int bk  = tid >> 5;          // B-load k row 0..7
    const int bn  = (tid & 31) * 4;    // B-load col

    ull acc2[4][8];
#pragma unroll
    for (int i = 0; i < 4; i++)
#pragma unroll
        for (int j = 0; j < 8; j++) acc2[i][j] = 0ull;

    const float* xrow = g_X + (size_t)(m0 + ar) * KTOT + ac;

    for (int k0 = 0; k0 < KTOT; k0 += 8) {
        float4 av = *(const float4*)(xrow + k0);
        float4 bv = *(const float4*)(g_Wc + (size_t)(k0 + bk) * D + bn);
        __syncthreads();
        As[ac + 0][ar] = av.x;
        As[ac + 1][ar] = av.y;
        As[ac + 2][ar] = av.z;
        As[ac + 3][ar] = av.w;
        *(float4*)&Bs[bk][bn] = bv;
        __syncthreads();
#pragma unroll
        for (int kk = 0; kk < 8; kk++) {
            // 4 row-pairs straight from shared (consecutive floats -> f32x2)
            ull a2[4];
            const ull* ap = (const ull*)&As[kk][ty * 8];
#pragma unroll
            for (int i = 0; i < 4; i++) a2[i] = ap[i];
            // 8 broadcast-packed b values (mov.b64 {r,r} rides the alu pipe)
            float b[8];
            *(float4*)(b)     = *(const float4*)&Bs[kk][tx * 8];
            *(float4*)(b + 4) = *(const float4*)&Bs[kk][tx * 8 + 4];
            ull b2[8];
#pragma unroll
            for (int j = 0; j < 8; j++) b2[j] = pack_dup(b[j]);
#pragma unroll
            for (int i = 0; i < 4; i++)
#pragma unroll
                for (int j = 0; j < 8; j++) fma2(acc2[i][j], a2[i], b2[j]);
        }
    }

    // epilogue: relu(acc + b_a[n] + flag[m]*b2[n])
    float bb[8], bmsg[8];
#pragma unroll
    for (int j = 0; j < 8; j++) {
        int n = tx * 8 + j;
        bb[j]   = bias_a[n];
        bmsg[j] = g_bias2[n];
    }
#pragma unroll
    for (int ip = 0; ip < 4; ip++) {
        int mA = m0 + ty * 8 + 2 * ip;
        int mB = mA + 1;
        float flA = (mA < N_NODES) ? g_flag[mA] : 0.f;
        float flB = (mB < N_NODES) ? g_flag[mB] : 0.f;
        float rA[8], rB[8];
#pragma unroll
        for (int j = 0; j < 8; j++) {
            float lo, hi;
            unpack2(acc2[ip][j], lo, hi);
            float vA = lo + bb[j] + flA * bmsg[j];
            float vB = hi + bb[j] + flB * bmsg[j];
            rA[j] = vA > 0.f ? vA : 0.f;
            rB[j] = vB > 0.f ? vB : 0.f;
        }
        if (mA < N_NODES) {
            *(float4*)&out[(size_t)mA * D + tx * 8]     = *(float4*)(rA);
            *(float4*)&out[(size_t)mA * D + tx * 8 + 4] = *(float4*)(rA + 4);
        }
        if (mB < N_NODES) {
            *(float4*)&out[(size_t)mB * D + tx * 8]     = *(float4*)(rB);
            *(float4*)&out[(size_t)mB * D + tx * 8 + 4] = *(float4*)(rB + 4);
        }
    }
}

// ---------------- launch -----------------------------------------------------
extern "C" void kernel_launch(void* const* d_in, const int* in_sizes, int n_in,
                              void* d_out, int out_size) {
    const float* nfeats = (const float*)d_in[0];
    const float* efeats = (const float*)d_in[1];
    const float* Wm     = (const float*)d_in[2];
    const float* bm     = (const float*)d_in[3];
    const float* Wa     = (const float*)d_in[4];
    const float* ba     = (const float*)d_in[5];
    const int*   src    = (const int*)d_in[6];
    const int*   dst    = (const int*)d_in[7];
    float* out = (float*)d_out;

    zero_kernel  <<<(N_NODES + 255) / 256, 256>>>();
    wc_kernel    <<<D, 256>>>(Wm, bm, Wa);
    count_kernel <<<(N_EDGES + 255) / 256, 256>>>(dst);
    scan1_kernel <<<NBLK_SCAN, 1024>>>();
    scan2_kernel <<<1, 32>>>();
    scan3_kernel <<<(N_NODES + 255) / 256, 256>>>();
    fill_kernel  <<<(N_EDGES + 255) / 256, 256>>>(dst);
    gather_kernel<<<(N_NODES * 32 + 255) / 256, 256>>>(nfeats, efeats, src);
    gemm_kernel  <<<M_PAD / 128, 256>>>(ba, out);
}